// round 6
// baseline (speedup 1.0000x reference)
#include <cuda_runtime.h>
#include <cstdint>

#define BB   8
#define NPTS 2048
#define KNN  10
#define MAXF 1024
#define SLOPE 0.2f
#define KPMAX 1536

// ---------------- static scratch (no allocations allowed) ----------------
__device__ float g_feat_a[BB * NPTS * MAXF];                  // 64 MB
__device__ float g_feat_b[BB * NPTS * MAXF];                  // 64 MB
__device__ float g_center[BB * NPTS * MAXF];                  // 64 MB
__device__ float g_dot[(size_t)BB * NPTS * NPTS];             // 128 MB (reused as Y after topk)
__device__ float g_xa[(size_t)BB * NPTS * KPMAX];             // 100 MB tf32 split (h,l,h)
__device__ float g_xb[(size_t)BB * NPTS * KPMAX];             // 100 MB tf32 split (h,h,l)
__device__ float g_w1t[1024 * KPMAX];                         // 6 MB  W1^T split (h,h,l)
__device__ float g_w2t[1024 * KPMAX];                         // 6 MB  W2^T split (h,h,l)
__device__ float g_sq[BB * NPTS];
__device__ int   g_idx[BB * NPTS * KNN];
__device__ float g_pool[BB * MAXF];
__device__ float g_m1[BB * 128];
__device__ float g_m2[BB * 64];

// ---------------- tf32 helpers ----------------
__device__ __forceinline__ uint32_t to_tf32(float x) {
    uint32_t r;
    asm("cvt.rna.tf32.f32 %0, %1;" : "=r"(r) : "f"(x));
    return r;
}

// =====================================================================
// conversions: fp32 -> 3-slot tf32 split
// X[M,fin] -> Xa[M,Kp] = (h,l,h,pad0) and Xb[M,Kp] = (h,h,l,pad0)
// =====================================================================
__global__ void convert_x(const float* __restrict__ X, float* __restrict__ Xa,
                          float* __restrict__ Xb, int fin, int Kp, int M) {
    int idx = blockIdx.x * blockDim.x + threadIdx.x;
    if (idx >= M * Kp) return;
    int r = idx / Kp, c = idx % Kp;
    float va = 0.f, vb = 0.f;
    if (c < 3 * fin) {
        int s = c / fin, cc = c - s * fin;
        float v = X[(size_t)r * fin + cc];
        float h = __uint_as_float(to_tf32(v));
        float l = __uint_as_float(to_tf32(v - h));
        va = (s == 1) ? l : h;
        vb = (s == 2) ? l : h;
    }
    Xa[(size_t)r * Kp + c] = va;
    Xb[(size_t)r * Kp + c] = vb;
}

// W[fin,fout] -> Wt[fout,Kp] = (h,h,l) transposed split (B-side layout)
__global__ void convert_w(const float* __restrict__ W, float* __restrict__ Wt,
                          int fin, int fout, int Kp) {
    int idx = blockIdx.x * blockDim.x + threadIdx.x;
    if (idx >= fout * Kp) return;
    int n = idx / Kp, c = idx % Kp;
    float o = 0.f;
    if (c < 3 * fin) {
        int s = c / fin, cc = c - s * fin;
        float v = W[(size_t)cc * fout + n];
        float h = __uint_as_float(to_tf32(v));
        o = (s == 2) ? __uint_as_float(to_tf32(v - h)) : h;
    }
    Wt[(size_t)n * Kp + c] = o;
}

// =====================================================================
// tf32 MMA core: 128x128 block, 8 warps (2M x 4N), m16n8k8, BK=32
// A row-major [rows][Kp], B row-major [cols][Kp] (row n = output col n).
// =====================================================================
#define MMA_TF32(c, a, b)                                                          \
    asm volatile("mma.sync.aligned.m16n8k8.row.col.f32.tf32.tf32.f32 "             \
                 "{%0,%1,%2,%3}, {%4,%5,%6,%7}, {%8,%9}, {%0,%1,%2,%3};"           \
                 : "+f"(c[0]), "+f"(c[1]), "+f"(c[2]), "+f"(c[3])                  \
                 : "r"(a[0]), "r"(a[1]), "r"(a[2]), "r"(a[3]), "r"(b[0]), "r"(b[1]))

__device__ __forceinline__ void tile_load(uint32_t (*S)[33], const float* __restrict__ src,
                                          int row0, int Kp, int k0, int tid) {
#pragma unroll
    for (int it = 0; it < 4; it++) {
        int e = tid + it * 256;          // 0..1023
        int r = e >> 3;
        int cb = (e & 7) * 4;
        uint4 v = *(const uint4*)(src + (size_t)(row0 + r) * Kp + k0 + cb);
        S[r][cb + 0] = v.x;
        S[r][cb + 1] = v.y;
        S[r][cb + 2] = v.z;
        S[r][cb + 3] = v.w;
    }
}

__device__ __forceinline__ void tile_mma(uint32_t (*As)[33], uint32_t (*Bs)[33],
                                         float acc[4][4][4], int wm, int wn,
                                         int g, int t) {
#pragma unroll
    for (int ks = 0; ks < 4; ks++) {
        int kb = ks * 8;
        uint32_t a[4][4];
#pragma unroll
        for (int mi = 0; mi < 4; mi++) {
            int rb = wm + mi * 16;
            a[mi][0] = As[rb + g][kb + t];
            a[mi][1] = As[rb + g + 8][kb + t];
            a[mi][2] = As[rb + g][kb + t + 4];
            a[mi][3] = As[rb + g + 8][kb + t + 4];
        }
        uint32_t bf[4][2];
#pragma unroll
        for (int ni = 0; ni < 4; ni++) {
            int nb = wn + ni * 8 + g;
            bf[ni][0] = Bs[nb][kb + t];
            bf[ni][1] = Bs[nb][kb + t + 4];
        }
#pragma unroll
        for (int mi = 0; mi < 4; mi++)
#pragma unroll
            for (int ni = 0; ni < 4; ni++) MMA_TF32(acc[mi][ni], a[mi], bf[ni]);
    }
}

// ---------------- NN: C[M,Nn] = Xa @ Wt^T (+bias) ----------------
__global__ __launch_bounds__(256) void mma_nn(const float* __restrict__ A,
                                              const float* __restrict__ B,
                                              const float* __restrict__ bias,
                                              float* __restrict__ C,
                                              int Kp, int Nn) {
    __shared__ uint32_t As[128][33];
    __shared__ uint32_t Bs[128][33];
    int tid = threadIdx.x;
    int m0 = blockIdx.y * 128, o0 = blockIdx.x * 128;
    int lane = tid & 31, warp = tid >> 5;
    int wm = (warp & 1) * 64, wn = (warp >> 1) * 32;
    int g = lane >> 2, t = lane & 3;

    float acc[4][4][4];
#pragma unroll
    for (int mi = 0; mi < 4; mi++)
#pragma unroll
        for (int ni = 0; ni < 4; ni++)
#pragma unroll
            for (int c = 0; c < 4; c++) acc[mi][ni][c] = 0.f;

    for (int k0 = 0; k0 < Kp; k0 += 32) {
        tile_load(As, A, m0, Kp, k0, tid);
        tile_load(Bs, B, o0, Kp, k0, tid);
        __syncthreads();
        tile_mma(As, Bs, acc, wm, wn, g, t);
        __syncthreads();
    }

#pragma unroll
    for (int mi = 0; mi < 4; mi++) {
        int row = m0 + wm + mi * 16 + g;
#pragma unroll
        for (int ni = 0; ni < 4; ni++) {
            int col = o0 + wn + ni * 8 + 2 * t;
            if (col < Nn) {
                float b0 = bias ? bias[col] : 0.f;
                float b1 = bias ? bias[col + 1] : 0.f;
                *(float2*)(C + (size_t)row * Nn + col) =
                    make_float2(acc[mi][ni][0] + b0, acc[mi][ni][1] + b1);
                *(float2*)(C + (size_t)(row + 8) * Nn + col) =
                    make_float2(acc[mi][ni][2] + b0, acc[mi][ni][3] + b1);
            }
        }
    }
}

// ---------------- NT per batch: dot = Xa_b @ Xb_b^T ----------------
__global__ __launch_bounds__(256) void mma_nt(const float* __restrict__ Xa,
                                              const float* __restrict__ Xb,
                                              float* __restrict__ Call, int Kp) {
    __shared__ uint32_t As[128][33];
    __shared__ uint32_t Bs[128][33];
    int b = blockIdx.z;
    const float* Ab = Xa + (size_t)b * NPTS * Kp;
    const float* Bb = Xb + (size_t)b * NPTS * Kp;
    float* C = Call + (size_t)b * NPTS * NPTS;
    int tid = threadIdx.x;
    int m0 = blockIdx.y * 128, n0 = blockIdx.x * 128;
    int lane = tid & 31, warp = tid >> 5;
    int wm = (warp & 1) * 64, wn = (warp >> 1) * 32;
    int g = lane >> 2, t = lane & 3;

    float acc[4][4][4];
#pragma unroll
    for (int mi = 0; mi < 4; mi++)
#pragma unroll
        for (int ni = 0; ni < 4; ni++)
#pragma unroll
            for (int c = 0; c < 4; c++) acc[mi][ni][c] = 0.f;

    for (int k0 = 0; k0 < Kp; k0 += 32) {
        tile_load(As, Ab, m0, Kp, k0, tid);
        tile_load(Bs, Bb, n0, Kp, k0, tid);
        __syncthreads();
        tile_mma(As, Bs, acc, wm, wn, g, t);
        __syncthreads();
    }

#pragma unroll
    for (int mi = 0; mi < 4; mi++) {
        int row = m0 + wm + mi * 16 + g;
#pragma unroll
        for (int ni = 0; ni < 4; ni++) {
            int col = n0 + wn + ni * 8 + 2 * t;
            *(float2*)(C + (size_t)row * NPTS + col) =
                make_float2(acc[mi][ni][0], acc[mi][ni][1]);
            *(float2*)(C + (size_t)(row + 8) * NPTS + col) =
                make_float2(acc[mi][ni][2], acc[mi][ni][3]);
        }
    }
}

// ---------------- squared norms ----------------
__global__ void sq_kernel(const float* __restrict__ X, int Kd) {
    int i = blockIdx.x * blockDim.x + threadIdx.x;
    if (i < BB * NPTS) {
        const float* p = X + (size_t)i * Kd;
        float s = 0.f;
        for (int f = 0; f < Kd; f++) s += p[f] * p[f];
        g_sq[i] = s;
    }
}

// ---------------- top-K smallest d2 per row, warp per row ----------------
__device__ __forceinline__ bool dless(float a, int ia, float bv, int ib) {
    return (a < bv) || (a == bv && ia < ib);
}

__global__ void topk_kernel(const float* __restrict__ dotm) {
    int gwarp = (blockIdx.x * blockDim.x + threadIdx.x) >> 5;
    int lane = threadIdx.x & 31;
    if (gwarp >= BB * NPTS) return;
    int b = gwarp / NPTS, i = gwarp % NPTS;
    const float* drow = dotm + ((size_t)b * NPTS + i) * NPTS;
    float sqi = g_sq[b * NPTS + i];

    float best[KNN];
    int bidx[KNN];
#pragma unroll
    for (int m = 0; m < KNN; m++) { best[m] = 3.0e38f; bidx[m] = 0x7fffffff; }

    for (int j = lane; j < NPTS; j += 32) {
        float d2 = sqi + g_sq[b * NPTS + j] - 2.0f * drow[j];
        if (dless(d2, j, best[KNN - 1], bidx[KNN - 1])) {
            int m = KNN - 1;
#pragma unroll
            for (int t = KNN - 1; t > 0; t--) {
                if (m == t && dless(d2, j, best[t - 1], bidx[t - 1])) {
                    best[t] = best[t - 1]; bidx[t] = bidx[t - 1]; m = t - 1;
                }
            }
            best[m] = d2; bidx[m] = j;
        }
    }

    int ptr = 0;
    for (int r = 0; r < KNN; r++) {
        float v = (ptr < KNN) ? best[ptr] : 3.0e38f;
        int jj = (ptr < KNN) ? bidx[ptr] : 0x7fffffff;
        float mv = v; int mj = jj;
#pragma unroll
        for (int off = 16; off > 0; off >>= 1) {
            float ov = __shfl_down_sync(0xffffffffu, mv, off);
            int oj = __shfl_down_sync(0xffffffffu, mj, off);
            if (dless(ov, oj, mv, mj)) { mv = ov; mj = oj; }
        }
        mv = __shfl_sync(0xffffffffu, mv, 0);
        mj = __shfl_sync(0xffffffffu, mj, 0);
        if (jj == mj && v == mv) ptr++;
        if (lane == 0) g_idx[((size_t)b * NPTS + i) * KNN + r] = mj;
    }
}

// ---------------- gather-max edge conv epilogue ----------------
// out[n,o] = leaky( Z[n,o] - Y[n,o] + max_{j in knn(n)} Y[j,o] )
__global__ __launch_bounds__(256) void gathermax_kernel(const float* __restrict__ Z,
                                                        const float* __restrict__ Y,
                                                        const int* __restrict__ idx,
                                                        float* __restrict__ Out,
                                                        int fout) {
    int bn = blockIdx.x;
    int b = bn >> 11;
    const int* ip = idx + (size_t)bn * KNN;
    __shared__ int nb[KNN];
    if (threadIdx.x < KNN) nb[threadIdx.x] = ip[threadIdx.x];
    __syncthreads();

    const float* Yb = Y + (size_t)b * NPTS * fout;
    size_t base = (size_t)bn * fout;

    for (int o = threadIdx.x * 4; o < fout; o += blockDim.x * 4) {
        float4 m = make_float4(-3.0e38f, -3.0e38f, -3.0e38f, -3.0e38f);
#pragma unroll
        for (int k = 0; k < KNN; k++) {
            float4 v = *(const float4*)(Yb + (size_t)nb[k] * fout + o);
            m.x = fmaxf(m.x, v.x);
            m.y = fmaxf(m.y, v.y);
            m.z = fmaxf(m.z, v.z);
            m.w = fmaxf(m.w, v.w);
        }
        float4 z = *(const float4*)(Z + base + o);
        float4 y = *(const float4*)(Y + base + o);
        float4 h;
        h.x = z.x - y.x + m.x;
        h.y = z.y - y.y + m.y;
        h.z = z.z - y.z + m.z;
        h.w = z.w - y.w + m.w;
        h.x = (h.x > 0.f) ? h.x : SLOPE * h.x;
        h.y = (h.y > 0.f) ? h.y : SLOPE * h.y;
        h.z = (h.z > 0.f) ? h.z : SLOPE * h.z;
        h.w = (h.w > 0.f) ? h.w : SLOPE * h.w;
        *(float4*)(Out + base + o) = h;
    }
}

// ---------------- global max pool over N ----------------
__global__ void pool_kernel(const float* __restrict__ H, int Fo) {
    int b = blockIdx.y;
    int o = blockIdx.x * blockDim.x + threadIdx.x;
    if (o < Fo) {
        float m = -3.0e38f;
        for (int n = 0; n < NPTS; n++)
            m = fmaxf(m, H[((size_t)b * NPTS + n) * Fo + o]);
        g_pool[b * Fo + o] = m;
    }
}

// ---------------- small MLP layer ----------------
__global__ void mlp_kernel(const float* __restrict__ A, const float* __restrict__ W,
                           const float* __restrict__ bias, float* __restrict__ C,
                           int M, int Kd, int Nn) {
    for (int i = threadIdx.x; i < M * Nn; i += blockDim.x) {
        int m = i / Nn, o = i % Nn;
        float s = bias[o];
        for (int f = 0; f < Kd; f++) s += A[(size_t)m * Kd + f] * W[(size_t)f * Nn + o];
        C[i] = s;
    }
}

// ---------------- launcher ----------------
extern "C" void kernel_launch(void* const* d_in, const int* in_sizes, int n_in,
                              void* d_out, int out_size) {
    const float* x = (const float*)d_in[0];
    const float* w[5];
    const float* bs[5];
    for (int l = 0; l < 5; l++) {
        w[l] = (const float*)d_in[1 + 2 * l];
        bs[l] = (const float*)d_in[2 + 2 * l];
    }
    const float* m0w = (const float*)d_in[11];
    const float* m0b = (const float*)d_in[12];
    const float* m1w = (const float*)d_in[13];
    const float* m1b = (const float*)d_in[14];
    const float* m2w = (const float*)d_in[15];
    const float* m2b = (const float*)d_in[16];
    float* out = (float*)d_out;

    float *feat_a, *feat_b, *centerp, *dotp, *poolp, *m1p, *m2p;
    float *xap, *xbp, *w1tp, *w2tp;
    cudaGetSymbolAddress((void**)&feat_a, g_feat_a);
    cudaGetSymbolAddress((void**)&feat_b, g_feat_b);
    cudaGetSymbolAddress((void**)&centerp, g_center);
    cudaGetSymbolAddress((void**)&dotp, g_dot);
    cudaGetSymbolAddress((void**)&poolp, g_pool);
    cudaGetSymbolAddress((void**)&m1p, g_m1);
    cudaGetSymbolAddress((void**)&m2p, g_m2);
    cudaGetSymbolAddress((void**)&xap, g_xa);
    cudaGetSymbolAddress((void**)&xbp, g_xb);
    cudaGetSymbolAddress((void**)&w1tp, g_w1t);
    cudaGetSymbolAddress((void**)&w2tp, g_w2t);
    int* idxp;
    cudaGetSymbolAddress((void**)&idxp, g_idx);

    const int fins[5] = {3, 64, 128, 256, 512};
    const int fouts[5] = {64, 128, 256, 512, 1024};
    float* bufs[2] = {feat_a, feat_b};
    const int M = BB * NPTS;

    const float* cur = x;
    for (int l = 0; l < 5; l++) {
        int fin = fins[l], fout = fouts[l];
        int Kp = ((3 * fin + 31) / 32) * 32;   // 32,192,384,768,1536
        float* yp = dotp;   // reuse dot scratch for Y after topk consumes it
        int gx = (fout + 127) / 128;

        // tf32 3-slot split conversions
        convert_x<<<(M * Kp + 255) / 256, 256>>>(cur, xap, xbp, fin, Kp, M);
        convert_w<<<(fout * Kp + 255) / 256, 256>>>(w[l], w1tp, fin, fout, Kp);
        convert_w<<<(fout * Kp + 255) / 256, 256>>>(w[l] + (size_t)fin * fout, w2tp,
                                                    fin, fout, Kp);

        // dot = X @ X^T (tensor cores, fp32-grade via 3-slot tf32)
        mma_nt<<<dim3(NPTS / 128, NPTS / 128, BB), 256>>>(xap, xbp, dotp, Kp);
        sq_kernel<<<(M + 255) / 256, 256>>>(cur, fin);
        topk_kernel<<<M / 8, 256>>>(dotp);

        // Z = X*W1 + b ; Y = X*W2
        mma_nn<<<dim3(gx, M / 128), 256>>>(xap, w1tp, bs[l], centerp, Kp, fout);
        mma_nn<<<dim3(gx, M / 128), 256>>>(xap, w2tp, nullptr, yp, Kp, fout);

        gathermax_kernel<<<M, 256>>>(centerp, yp, idxp, bufs[l & 1], fout);
        cur = bufs[l & 1];
    }

    pool_kernel<<<dim3(MAXF / 256, BB), 256>>>(cur, MAXF);
    mlp_kernel<<<1, 1024>>>(poolp, m0w, m0b, m1p, BB, 1024, 128);
    mlp_kernel<<<1, 512>>>(m1p, m1w, m1b, m2p, BB, 128, 64);
    mlp_kernel<<<1, 256>>>(m2p, m2w, m2b, out, BB, 64, 1);
}

// round 7
// speedup vs baseline: 1.9335x; 1.9335x over previous
#include <cuda_runtime.h>
#include <cuda_bf16.h>
#include <cstdint>

#define BB   8
#define NPTS 2048
#define KNN  10
#define MAXF 1024
#define SLOPE 0.2f
#define KPMAX 1536
#define SMPAD 40   // smem row stride in bf16 (conflict-free for ldmatrix)

// ---------------- static scratch (no allocations allowed) ----------------
__device__ float g_feat_a[BB * NPTS * MAXF];
__device__ float g_feat_b[BB * NPTS * MAXF];
__device__ float g_center[BB * NPTS * MAXF];
__device__ float g_dot[(size_t)BB * NPTS * NPTS];
__device__ __align__(16) __nv_bfloat16 g_xa[(size_t)BB * NPTS * KPMAX];  // (h,l,h)
__device__ __align__(16) __nv_bfloat16 g_xb[(size_t)BB * NPTS * KPMAX];  // (h,h,l)
__device__ __align__(16) __nv_bfloat16 g_w1t[1024 * KPMAX];              // (h,h,l) W1^T
__device__ __align__(16) __nv_bfloat16 g_w2t[1024 * KPMAX];              // (h,h,l) W2^T
__device__ float g_sq[BB * NPTS];
__device__ int   g_idx[BB * NPTS * KNN];
__device__ float g_pool[BB * MAXF];
__device__ float g_m1[BB * 128];
__device__ float g_m2[BB * 64];

// =====================================================================
// conversions: fp32 -> 3-slot bf16 split
// =====================================================================
__global__ void convert_x(const float* __restrict__ X, __nv_bfloat16* __restrict__ Xa,
                          __nv_bfloat16* __restrict__ Xb, int fin, int Kp, int M) {
    int idx = blockIdx.x * blockDim.x + threadIdx.x;
    if (idx >= M * Kp) return;
    int r = idx / Kp, c = idx % Kp;
    __nv_bfloat16 va = __float2bfloat16(0.f), vb = va;
    if (c < 3 * fin) {
        int s = c / fin, cc = c - s * fin;
        float v = X[(size_t)r * fin + cc];
        __nv_bfloat16 h = __float2bfloat16(v);
        __nv_bfloat16 l = __float2bfloat16(v - __bfloat162float(h));
        va = (s == 1) ? l : h;
        vb = (s == 2) ? l : h;
    }
    Xa[(size_t)r * Kp + c] = va;
    Xb[(size_t)r * Kp + c] = vb;
}

__global__ void convert_w(const float* __restrict__ W, __nv_bfloat16* __restrict__ Wt,
                          int fin, int fout, int Kp) {
    int idx = blockIdx.x * blockDim.x + threadIdx.x;
    if (idx >= fout * Kp) return;
    int n = idx / Kp, c = idx % Kp;
    __nv_bfloat16 o = __float2bfloat16(0.f);
    if (c < 3 * fin) {
        int s = c / fin, cc = c - s * fin;
        float v = W[(size_t)cc * fout + n];
        __nv_bfloat16 h = __float2bfloat16(v);
        o = (s == 2) ? __float2bfloat16(v - __bfloat162float(h)) : h;
    }
    Wt[(size_t)n * Kp + c] = o;
}

// =====================================================================
// bf16 MMA core with ldmatrix + cp.async, 128x128 block, 8 warps (2Mx4N)
// A row-major [rows][Kp], B row-major [cols][Kp], BK=32.
// =====================================================================
#define MMA_BF16(c, a, b)                                                          \
    asm volatile("mma.sync.aligned.m16n8k16.row.col.f32.bf16.bf16.f32 "            \
                 "{%0,%1,%2,%3}, {%4,%5,%6,%7}, {%8,%9}, {%0,%1,%2,%3};"           \
                 : "+f"(c[0]), "+f"(c[1]), "+f"(c[2]), "+f"(c[3])                  \
                 : "r"(a[0]), "r"(a[1]), "r"(a[2]), "r"(a[3]), "r"(b[0]), "r"(b[1]))

__device__ __forceinline__ void cpa16(void* smem, const void* gmem) {
    uint32_t s = (uint32_t)__cvta_generic_to_shared(smem);
    asm volatile("cp.async.ca.shared.global [%0], [%1], 16;" :: "r"(s), "l"(gmem));
}
__device__ __forceinline__ void ldsm_x4(uint32_t* r, const void* p) {
    uint32_t a = (uint32_t)__cvta_generic_to_shared(p);
    asm volatile("ldmatrix.sync.aligned.m8n8.x4.shared.b16 {%0,%1,%2,%3}, [%4];"
                 : "=r"(r[0]), "=r"(r[1]), "=r"(r[2]), "=r"(r[3]) : "r"(a));
}
__device__ __forceinline__ void ldsm_x2(uint32_t* r, const void* p) {
    uint32_t a = (uint32_t)__cvta_generic_to_shared(p);
    asm volatile("ldmatrix.sync.aligned.m8n8.x2.shared.b16 {%0,%1}, [%2];"
                 : "=r"(r[0]), "=r"(r[1]) : "r"(a));
}

// load one 128x32 bf16 tile into smem stage via cp.async
__device__ __forceinline__ void stage_load(__nv_bfloat16 (*S)[SMPAD],
                                           const __nv_bfloat16* __restrict__ src,
                                           int row0, int Kp, int k0, int tid) {
#pragma unroll
    for (int it = 0; it < 2; it++) {
        int e = tid + it * 256;          // 0..511
        int r = e >> 2;
        int cb = (e & 3) * 8;
        cpa16(&S[r][cb], src + (size_t)(row0 + r) * Kp + k0 + cb);
    }
}

// compute one BK=32 stage
__device__ __forceinline__ void stage_mma(const __nv_bfloat16 (*As)[SMPAD],
                                          const __nv_bfloat16 (*Bs)[SMPAD],
                                          float acc[4][4][4], int wm, int wn, int lane) {
    int a_row = (lane & 15);
    int a_col = (lane >> 4) * 8;
    int b_row = (lane & 7);
    int b_col = ((lane >> 3) & 1) * 8;
#pragma unroll
    for (int ks = 0; ks < 2; ks++) {
        int kb = ks * 16;
        uint32_t ar[4][4], br[4][2];
#pragma unroll
        for (int mi = 0; mi < 4; mi++)
            ldsm_x4(ar[mi], &As[wm + mi * 16 + a_row][kb + a_col]);
#pragma unroll
        for (int ni = 0; ni < 4; ni++)
            ldsm_x2(br[ni], &Bs[wn + ni * 8 + b_row][kb + b_col]);
#pragma unroll
        for (int mi = 0; mi < 4; mi++)
#pragma unroll
            for (int ni = 0; ni < 4; ni++) MMA_BF16(acc[mi][ni], ar[mi], br[ni]);
    }
}

// ---------------- NN: C[M,Nn] = Xa @ Wt^T (+bias) ----------------
__global__ __launch_bounds__(256) void mma_nn(const __nv_bfloat16* __restrict__ A,
                                              const __nv_bfloat16* __restrict__ B,
                                              const float* __restrict__ bias,
                                              float* __restrict__ C,
                                              int Kp, int Nn) {
    __shared__ __align__(16) __nv_bfloat16 As[2][128][SMPAD];
    __shared__ __align__(16) __nv_bfloat16 Bs[2][128][SMPAD];
    int tid = threadIdx.x;
    int m0 = blockIdx.y * 128, o0 = blockIdx.x * 128;
    int lane = tid & 31, warp = tid >> 5;
    int wm = (warp & 1) * 64, wn = (warp >> 1) * 32;
    int nk = Kp / 32;

    float acc[4][4][4];
#pragma unroll
    for (int mi = 0; mi < 4; mi++)
#pragma unroll
        for (int ni = 0; ni < 4; ni++)
#pragma unroll
            for (int c = 0; c < 4; c++) acc[mi][ni][c] = 0.f;

    stage_load(As[0], A, m0, Kp, 0, tid);
    stage_load(Bs[0], B, o0, Kp, 0, tid);
    asm volatile("cp.async.commit_group;");

    for (int kt = 0; kt < nk; kt++) {
        if (kt + 1 < nk) {
            stage_load(As[(kt + 1) & 1], A, m0, Kp, (kt + 1) * 32, tid);
            stage_load(Bs[(kt + 1) & 1], B, o0, Kp, (kt + 1) * 32, tid);
            asm volatile("cp.async.commit_group;");
            asm volatile("cp.async.wait_group 1;");
        } else {
            asm volatile("cp.async.wait_group 0;");
        }
        __syncthreads();
        stage_mma(As[kt & 1], Bs[kt & 1], acc, wm, wn, lane);
        __syncthreads();
    }

    int g = lane >> 2, t = lane & 3;
#pragma unroll
    for (int mi = 0; mi < 4; mi++) {
        int row = m0 + wm + mi * 16 + g;
#pragma unroll
        for (int ni = 0; ni < 4; ni++) {
            int col = o0 + wn + ni * 8 + 2 * t;
            if (col < Nn) {
                float b0 = bias ? bias[col] : 0.f;
                float b1 = bias ? bias[col + 1] : 0.f;
                *(float2*)(C + (size_t)row * Nn + col) =
                    make_float2(acc[mi][ni][0] + b0, acc[mi][ni][1] + b1);
                *(float2*)(C + (size_t)(row + 8) * Nn + col) =
                    make_float2(acc[mi][ni][2] + b0, acc[mi][ni][3] + b1);
            }
        }
    }
}

// ---------------- NT per batch: dot = Xa_b @ Xb_b^T ----------------
__global__ __launch_bounds__(256) void mma_nt(const __nv_bfloat16* __restrict__ Xa,
                                              const __nv_bfloat16* __restrict__ Xb,
                                              float* __restrict__ Call, int Kp) {
    __shared__ __align__(16) __nv_bfloat16 As[2][128][SMPAD];
    __shared__ __align__(16) __nv_bfloat16 Bs[2][128][SMPAD];
    int b = blockIdx.z;
    const __nv_bfloat16* Ab = Xa + (size_t)b * NPTS * Kp;
    const __nv_bfloat16* Bb = Xb + (size_t)b * NPTS * Kp;
    float* C = Call + (size_t)b * NPTS * NPTS;
    int tid = threadIdx.x;
    int m0 = blockIdx.y * 128, n0 = blockIdx.x * 128;
    int lane = tid & 31, warp = tid >> 5;
    int wm = (warp & 1) * 64, wn = (warp >> 1) * 32;
    int nk = Kp / 32;

    float acc[4][4][4];
#pragma unroll
    for (int mi = 0; mi < 4; mi++)
#pragma unroll
        for (int ni = 0; ni < 4; ni++)
#pragma unroll
            for (int c = 0; c < 4; c++) acc[mi][ni][c] = 0.f;

    stage_load(As[0], Ab, m0, Kp, 0, tid);
    stage_load(Bs[0], Bb, n0, Kp, 0, tid);
    asm volatile("cp.async.commit_group;");

    for (int kt = 0; kt < nk; kt++) {
        if (kt + 1 < nk) {
            stage_load(As[(kt + 1) & 1], Ab, m0, Kp, (kt + 1) * 32, tid);
            stage_load(Bs[(kt + 1) & 1], Bb, n0, Kp, (kt + 1) * 32, tid);
            asm volatile("cp.async.commit_group;");
            asm volatile("cp.async.wait_group 1;");
        } else {
            asm volatile("cp.async.wait_group 0;");
        }
        __syncthreads();
        stage_mma(As[kt & 1], Bs[kt & 1], acc, wm, wn, lane);
        __syncthreads();
    }

    int g = lane >> 2, t = lane & 3;
#pragma unroll
    for (int mi = 0; mi < 4; mi++) {
        int row = m0 + wm + mi * 16 + g;
#pragma unroll
        for (int ni = 0; ni < 4; ni++) {
            int col = n0 + wn + ni * 8 + 2 * t;
            *(float2*)(C + (size_t)row * NPTS + col) =
                make_float2(acc[mi][ni][0], acc[mi][ni][1]);
            *(float2*)(C + (size_t)(row + 8) * NPTS + col) =
                make_float2(acc[mi][ni][2], acc[mi][ni][3]);
        }
    }
}

// ---------------- squared norms ----------------
__global__ void sq_kernel(const float* __restrict__ X, int Kd) {
    int i = blockIdx.x * blockDim.x + threadIdx.x;
    if (i < BB * NPTS) {
        const float* p = X + (size_t)i * Kd;
        float s = 0.f;
        for (int f = 0; f < Kd; f++) s += p[f] * p[f];
        g_sq[i] = s;
    }
}

// ---------------- top-K smallest d2 per row, warp per row ----------------
__device__ __forceinline__ bool dless(float a, int ia, float bv, int ib) {
    return (a < bv) || (a == bv && ia < ib);
}

__global__ void topk_kernel(const float* __restrict__ dotm) {
    int gwarp = (blockIdx.x * blockDim.x + threadIdx.x) >> 5;
    int lane = threadIdx.x & 31;
    if (gwarp >= BB * NPTS) return;
    int b = gwarp / NPTS, i = gwarp % NPTS;
    const float* drow = dotm + ((size_t)b * NPTS + i) * NPTS;
    float sqi = g_sq[b * NPTS + i];

    float best[KNN];
    int bidx[KNN];
#pragma unroll
    for (int m = 0; m < KNN; m++) { best[m] = 3.0e38f; bidx[m] = 0x7fffffff; }

    for (int j = lane; j < NPTS; j += 32) {
        float d2 = sqi + g_sq[b * NPTS + j] - 2.0f * drow[j];
        if (dless(d2, j, best[KNN - 1], bidx[KNN - 1])) {
            int m = KNN - 1;
#pragma unroll
            for (int t = KNN - 1; t > 0; t--) {
                if (m == t && dless(d2, j, best[t - 1], bidx[t - 1])) {
                    best[t] = best[t - 1]; bidx[t] = bidx[t - 1]; m = t - 1;
                }
            }
            best[m] = d2; bidx[m] = j;
        }
    }

    int ptr = 0;
    for (int r = 0; r < KNN; r++) {
        float v = (ptr < KNN) ? best[ptr] : 3.0e38f;
        int jj = (ptr < KNN) ? bidx[ptr] : 0x7fffffff;
        float mv = v; int mj = jj;
#pragma unroll
        for (int off = 16; off > 0; off >>= 1) {
            float ov = __shfl_down_sync(0xffffffffu, mv, off);
            int oj = __shfl_down_sync(0xffffffffu, mj, off);
            if (dless(ov, oj, mv, mj)) { mv = ov; mj = oj; }
        }
        mv = __shfl_sync(0xffffffffu, mv, 0);
        mj = __shfl_sync(0xffffffffu, mj, 0);
        if (jj == mj && v == mv) ptr++;
        if (lane == 0) g_idx[((size_t)b * NPTS + i) * KNN + r] = mj;
    }
}

// ---------------- gather-max edge conv epilogue ----------------
__global__ __launch_bounds__(256) void gathermax_kernel(const float* __restrict__ Z,
                                                        const float* __restrict__ Y,
                                                        const int* __restrict__ idx,
                                                        float* __restrict__ Out,
                                                        int fout) {
    int bn = blockIdx.x;
    int b = bn >> 11;
    const int* ip = idx + (size_t)bn * KNN;
    __shared__ int nb[KNN];
    if (threadIdx.x < KNN) nb[threadIdx.x] = ip[threadIdx.x];
    __syncthreads();

    const float* Yb = Y + (size_t)b * NPTS * fout;
    size_t base = (size_t)bn * fout;

    for (int o = threadIdx.x * 4; o < fout; o += blockDim.x * 4) {
        float4 m = make_float4(-3.0e38f, -3.0e38f, -3.0e38f, -3.0e38f);
#pragma unroll
        for (int k = 0; k < KNN; k++) {
            float4 v = *(const float4*)(Yb + (size_t)nb[k] * fout + o);
            m.x = fmaxf(m.x, v.x);
            m.y = fmaxf(m.y, v.y);
            m.z = fmaxf(m.z, v.z);
            m.w = fmaxf(m.w, v.w);
        }
        float4 z = *(const float4*)(Z + base + o);
        float4 y = *(const float4*)(Y + base + o);
        float4 h;
        h.x = z.x - y.x + m.x;
        h.y = z.y - y.y + m.y;
        h.z = z.z - y.z + m.z;
        h.w = z.w - y.w + m.w;
        h.x = (h.x > 0.f) ? h.x : SLOPE * h.x;
        h.y = (h.y > 0.f) ? h.y : SLOPE * h.y;
        h.z = (h.z > 0.f) ? h.z : SLOPE * h.z;
        h.w = (h.w > 0.f) ? h.w : SLOPE * h.w;
        *(float4*)(Out + base + o) = h;
    }
}

// ---------------- global max pool over N ----------------
__global__ void pool_kernel(const float* __restrict__ H, int Fo) {
    int b = blockIdx.y;
    int o = blockIdx.x * blockDim.x + threadIdx.x;
    if (o < Fo) {
        float m = -3.0e38f;
        for (int n = 0; n < NPTS; n++)
            m = fmaxf(m, H[((size_t)b * NPTS + n) * Fo + o]);
        g_pool[b * Fo + o] = m;
    }
}

// ---------------- small MLP layer ----------------
__global__ void mlp_kernel(const float* __restrict__ A, const float* __restrict__ W,
                           const float* __restrict__ bias, float* __restrict__ C,
                           int M, int Kd, int Nn) {
    for (int i = threadIdx.x; i < M * Nn; i += blockDim.x) {
        int m = i / Nn, o = i % Nn;
        float s = bias[o];
        for (int f = 0; f < Kd; f++) s += A[(size_t)m * Kd + f] * W[(size_t)f * Nn + o];
        C[i] = s;
    }
}

// ---------------- launcher ----------------
extern "C" void kernel_launch(void* const* d_in, const int* in_sizes, int n_in,
                              void* d_out, int out_size) {
    const float* x = (const float*)d_in[0];
    const float* w[5];
    const float* bs[5];
    for (int l = 0; l < 5; l++) {
        w[l] = (const float*)d_in[1 + 2 * l];
        bs[l] = (const float*)d_in[2 + 2 * l];
    }
    const float* m0w = (const float*)d_in[11];
    const float* m0b = (const float*)d_in[12];
    const float* m1w = (const float*)d_in[13];
    const float* m1b = (const float*)d_in[14];
    const float* m2w = (const float*)d_in[15];
    const float* m2b = (const float*)d_in[16];
    float* out = (float*)d_out;

    float *feat_a, *feat_b, *centerp, *dotp, *poolp, *m1p, *m2p;
    __nv_bfloat16 *xap, *xbp, *w1tp, *w2tp;
    cudaGetSymbolAddress((void**)&feat_a, g_feat_a);
    cudaGetSymbolAddress((void**)&feat_b, g_feat_b);
    cudaGetSymbolAddress((void**)&centerp, g_center);
    cudaGetSymbolAddress((void**)&dotp, g_dot);
    cudaGetSymbolAddress((void**)&poolp, g_pool);
    cudaGetSymbolAddress((void**)&m1p, g_m1);
    cudaGetSymbolAddress((void**)&m2p, g_m2);
    cudaGetSymbolAddress((void**)&xap, g_xa);
    cudaGetSymbolAddress((void**)&xbp, g_xb);
    cudaGetSymbolAddress((void**)&w1tp, g_w1t);
    cudaGetSymbolAddress((void**)&w2tp, g_w2t);
    int* idxp;
    cudaGetSymbolAddress((void**)&idxp, g_idx);

    const int fins[5] = {3, 64, 128, 256, 512};
    const int fouts[5] = {64, 128, 256, 512, 1024};
    float* bufs[2] = {feat_a, feat_b};
    const int M = BB * NPTS;

    const float* cur = x;
    for (int l = 0; l < 5; l++) {
        int fin = fins[l], fout = fouts[l];
        int Kp = ((3 * fin + 31) / 32) * 32;   // 32,192,384,768,1536
        float* yp = dotp;
        int gx = (fout + 127) / 128;

        convert_x<<<(M * Kp + 255) / 256, 256>>>(cur, xap, xbp, fin, Kp, M);
        convert_w<<<(fout * Kp + 255) / 256, 256>>>(w[l], w1tp, fin, fout, Kp);
        convert_w<<<(fout * Kp + 255) / 256, 256>>>(w[l] + (size_t)fin * fout, w2tp,
                                                    fin, fout, Kp);

        mma_nt<<<dim3(NPTS / 128, NPTS / 128, BB), 256>>>(xap, xbp, dotp, Kp);
        sq_kernel<<<(M + 255) / 256, 256>>>(cur, fin);
        topk_kernel<<<M / 8, 256>>>(dotp);

        mma_nn<<<dim3(gx, M / 128), 256>>>(xap, w1tp, bs[l], centerp, Kp, fout);
        mma_nn<<<dim3(gx, M / 128), 256>>>(xap, w2tp, nullptr, yp, Kp, fout);

        gathermax_kernel<<<M, 256>>>(centerp, yp, idxp, bufs[l & 1], fout);
        cur = bufs[l & 1];
    }

    pool_kernel<<<dim3(MAXF / 256, BB), 256>>>(cur, MAXF);
    mlp_kernel<<<1, 1024>>>(poolp, m0w, m0b, m1p, BB, 1024, 128);
    mlp_kernel<<<1, 512>>>(m1p, m1w, m1b, m2p, BB, 128, 64);
    mlp_kernel<<<1, 256>>>(m2p, m2w, m2b, out, BB, 64, 1);
}